// round 15
// baseline (speedup 1.0000x reference)
#include <cuda_runtime.h>

#define NUM_SKILLS 300
#define EMB 256
#define CD 64
#define BB 512
#define SS 200
#define RPB 40                     // rows per store block
#define SEGS (SS / RPB)            // 5 store blocks per batch row
#define NCOEF_BLKS 32              // coefficient blocks (8 warps * 32 = 256 e)
#define NSEG 7                     // 7 warp-segments of 32 cover 224 >= 200

// Scratch (no allocations allowed).
__device__ float g_A[EMB], g_B[EMB], g_C[EMB], g_D[EMB];
__device__ int   g_done;           // monotonic across graph replays

// ---------------------------------------------------------------------------
// Single fused kernel, grid 2592.
// Blocks 0..31 (wave 1, no dependencies): einsum-collapse coefficients,
//   one warp per e; then fence + counter bump.
//   out[b,s,e] = qf*A[e] + att*B[e] + mast*C[e] + valid*D[e]
// Blocks 32..2591: store block = (batch b, 40-row segment).
//   Phase A: in-block running counts over the row prefix (match_any +
//            lanemask_le within 32-wide warp segments; cross-segment via
//            per-warp packed histograms in shared). ~500 cycles.
//   Phase B: thread 0 spins on g_done (free after first replay), sync.
//   Phase C: store loop — e4 = t&63 holds 4 coefficient float4s in regs,
//            10 iterations of (broadcast LDS + 12 FMA + STG.128).
// ---------------------------------------------------------------------------
__global__ void __launch_bounds__(256) fused_kernel(
    const int* __restrict__ q, const int* __restrict__ r,
    const float* __restrict__ skill_w, const float* __restrict__ skill_b,
    const float* __restrict__ att_w,   const float* __restrict__ att_b,
    const float* __restrict__ mast_w,  const float* __restrict__ mast_b,
    const float* __restrict__ proj_w,  const float* __restrict__ proj_b,
    float* __restrict__ out)
{
    const int blk  = blockIdx.x;
    const int t    = threadIdx.x;
    const int w    = t >> 5;
    const int lane = t & 31;

    if (blk < NCOEF_BLKS) {
        // ---- coefficients: e = blk*8 + warp ----
        const int e   = blk * 8 + w;             // 0..255
        const int chi = lane + 32;

        const float wlo = (lane < 21) ? skill_w[lane] : att_w[lane - 21];
        const float blo = (lane < 21) ? skill_b[lane] : att_b[lane - 21];
        const float whi = (chi  < 42) ? att_w[chi - 21] : mast_w[chi - 42];
        const float bhi = (chi  < 42) ? att_b[chi - 21] : mast_b[chi - 42];

        const float p0 = proj_w[e * CD + lane];
        const float p1 = proj_w[e * CD + chi];

        const bool loA = lane < 21;
        const bool hiB = chi  < 42;

        float av = loA ? p0 * wlo : 0.0f;
        float bv = (loA ? 0.0f : p0 * wlo) + (hiB ? p1 * whi : 0.0f);
        float cv = hiB ? 0.0f : p1 * whi;
        float dv = fmaf(p0, blo, p1 * bhi);

        #pragma unroll
        for (int off = 16; off > 0; off >>= 1) {
            av += __shfl_xor_sync(0xFFFFFFFF, av, off);
            bv += __shfl_xor_sync(0xFFFFFFFF, bv, off);
            cv += __shfl_xor_sync(0xFFFFFFFF, cv, off);
            dv += __shfl_xor_sync(0xFFFFFFFF, dv, off);
        }
        if (lane == 0) {
            g_A[e] = av; g_B[e] = bv; g_C[e] = cv;
            g_D[e] = dv + proj_b[e];
        }
        __syncthreads();                          // all 8 warps' writes issued
        if (t == 0) {
            __threadfence();                      // publish before counting
            atomicAdd(&g_done, 1);
        }
        return;
    }

    // ---------------- store block ----------------
    __shared__ unsigned hist[NSEG][NUM_SKILLS + 4];   // att | cor<<16
    __shared__ float4   scal[RPB];                    // {qf, att, mast, valid}

    const int sb = blk - NCOEF_BLKS;
    const int b  = sb / SEGS;
    const int s0 = (sb % SEGS) * RPB;
    const int n  = s0 + RPB;                     // prefix length needed

    // zero histograms (7*304/2 = 1064 uint2)
    {
        uint2* hz2 = reinterpret_cast<uint2*>(&hist[0][0]);
        #pragma unroll
        for (int i = 0; i < 5; ++i) {
            const int idx = t + i * 256;
            if (idx < NSEG * (NUM_SKILLS + 4) / 2) hz2[idx] = make_uint2(0u, 0u);
        }
    }

    // Phase A inputs: element e == t of this batch row's prefix.
    int valid = 0, key = 0x8000 | t, rb = 0;
    if (t < n) {
        const int qraw = q[b * SS + t];
        valid = (qraw >= 0) & (qraw < NUM_SKILLS);
        if (valid) {
            key = qraw;
            rb  = r[b * SS + t] & 1;
        }
    }
    __syncthreads();                              // histograms zeroed

    // within-segment running counts (self included)
    const unsigned mask  = __match_any_sync(0xFFFFFFFFu, key);
    const unsigned rball = __ballot_sync(0xFFFFFFFFu, rb);
    const unsigned le    = (lane == 31) ? 0xFFFFFFFFu : ((2u << lane) - 1u);
    int att = __popc(mask & le);
    int cor = __popc(mask & le & rball);

    if (valid) atomicAdd(&hist[w][key], 1u | ((unsigned)rb << 16));

    // Phase B: wait for coefficients (thread 0; free after first replay).
    if (t == 0) {
        while (atomicAdd(&g_done, 0) < NCOEF_BLKS) __nanosleep(64);
        __threadfence();
    }
    __syncthreads();                              // hist done + coeffs ready

    // resolve this block's rows
    if (t >= s0 && t < n) {
        if (valid) {
            unsigned acc = 0;
            for (int gp = 0; gp < w; ++gp) acc += hist[gp][key];
            att += (int)(acc & 0xFFFFu);
            cor += (int)(acc >> 16);
            const float attf = (float)att;
            scal[t - s0] = make_float4((float)key, attf,
                                       (float)cor / fmaxf(attf, 1.0f), 1.0f);
        } else {
            scal[t - s0] = make_float4(0.f, 0.f, 0.f, 0.f);
        }
    }

    // Phase C prologue: coefficient fetch (after the sync above).
    const int e4 = t & 63;
    const int l4 = t >> 6;                       // 0..3
    const float4 a  = __ldg(&reinterpret_cast<const float4*>(g_A)[e4]);
    const float4 bc = __ldg(&reinterpret_cast<const float4*>(g_B)[e4]);
    const float4 cc = __ldg(&reinterpret_cast<const float4*>(g_C)[e4]);
    const float4 dc = __ldg(&reinterpret_cast<const float4*>(g_D)[e4]);
    __syncthreads();                              // scal[] complete

    float4* __restrict__ out4 = reinterpret_cast<float4*>(out);
    const int base = (b * SS + s0) * (EMB / 4) + e4;

    #pragma unroll
    for (int i = 0; i < RPB / 4; ++i) {
        const int row = l4 + i * 4;              // 0..39, uniform per warp
        const float4 s = scal[row];              // LDS broadcast
        float4 o;
        o.x = fmaf(s.x, a.x, fmaf(s.y, bc.x, fmaf(s.z, cc.x, s.w * dc.x)));
        o.y = fmaf(s.x, a.y, fmaf(s.y, bc.y, fmaf(s.z, cc.y, s.w * dc.y)));
        o.z = fmaf(s.x, a.z, fmaf(s.y, bc.z, fmaf(s.z, cc.z, s.w * dc.z)));
        o.w = fmaf(s.x, a.w, fmaf(s.y, bc.w, fmaf(s.z, cc.w, s.w * dc.w)));
        out4[base + row * (EMB / 4)] = o;
    }
}

// Input order (metadata): 0=q 1=r 2=qry(unused) 3=skill_w 4=skill_b
// 5=att_w 6=att_b 7=mast_w 8=mast_b 9=proj_w 10=proj_b
extern "C" void kernel_launch(void* const* d_in, const int* in_sizes, int n_in,
                              void* d_out, int out_size)
{
    const int*   q       = (const int*)d_in[0];
    const int*   r       = (const int*)d_in[1];
    const float* skill_w = (const float*)d_in[3];
    const float* skill_b = (const float*)d_in[4];
    const float* att_w   = (const float*)d_in[5];
    const float* att_b   = (const float*)d_in[6];
    const float* mast_w  = (const float*)d_in[7];
    const float* mast_b  = (const float*)d_in[8];
    const float* proj_w  = (const float*)d_in[9];
    const float* proj_b  = (const float*)d_in[10];
    float* out = (float*)d_out;

    fused_kernel<<<NCOEF_BLKS + BB * SEGS, 256>>>(
        q, r, skill_w, skill_b, att_w, att_b,
        mast_w, mast_b, proj_w, proj_b, out);    // 2592 blocks, ONE launch
}